// round 1
// baseline (speedup 1.0000x reference)
#include <cuda_runtime.h>
#include <math.h>

// Problem constants
#define NN 512
#define CC 128
#define MM (NN*NN)          // 262144 rows

// ---------------- scratch (device globals: allocation-free) ----------------
// channel-major a/b: (C, N, N)  -> 128 MB each
__device__ float g_AT[(size_t)CC * MM];
__device__ float g_BT[(size_t)CC * MM];
// sigmoid(x @ Wgl^T): (M, C)
__device__ float g_GL[(size_t)CC * MM];
// triangle result channel-major (C, N, N) and row-major (M, C)
__device__ float g_TRIT[(size_t)CC * MM];
__device__ float g_TRI [(size_t)CC * MM];
// layernorm stats
__device__ float g_mu1[MM];
__device__ float g_rs1[MM];
__device__ float g_mu2[MM];
__device__ float g_rs2[MM];

__device__ __forceinline__ float sigmoidf_(float x) {
    return 1.0f / (1.0f + expf(-x));
}

// ---------------- LN row stats: one warp per 128-float row ----------------
__global__ __launch_bounds__(256) void k_stats(const float* __restrict__ src, int which) {
    const float* __restrict__ s = which ? (const float*)g_TRI : src;
    float* __restrict__ mu = which ? g_mu2 : g_mu1;
    float* __restrict__ rs = which ? g_rs2 : g_rs1;

    int row  = blockIdx.x * 8 + (threadIdx.x >> 5);
    int lane = threadIdx.x & 31;
    float4 v = reinterpret_cast<const float4*>(s + (size_t)row * CC)[lane];
    float sm = v.x + v.y + v.z + v.w;
    #pragma unroll
    for (int o = 16; o > 0; o >>= 1) sm += __shfl_xor_sync(0xffffffffu, sm, o);
    float m = sm * (1.0f / CC);
    float dx = v.x - m, dy = v.y - m, dz = v.z - m, dw = v.w - m;
    float q = dx*dx + dy*dy + dz*dz + dw*dw;
    #pragma unroll
    for (int o = 16; o > 0; o >>= 1) q += __shfl_xor_sync(0xffffffffu, q, o);
    if (lane == 0) {
        mu[row] = m;
        rs[row] = rsqrtf(q * (1.0f / CC) + 1e-5f);
    }
}

// ---------------- proj/gate GEMM, fused LN1 + mask + sigmoid gate ----------
// Computes a[c] = (x@Wp^T)[2c+off] * mask * sigmoid((x@Wg^T)[2c+off])
// for a 128-row x 64-channel tile; writes channel-major to g_AT (off=0) / g_BT (off=1).
__global__ __launch_bounds__(256) void k_proj(const float* __restrict__ pair,
                                              const float* __restrict__ mask,
                                              const float* __restrict__ w1,
                                              const float* __restrict__ b1,
                                              const float* __restrict__ Wp,
                                              const float* __restrict__ Wg) {
    __shared__ float Xs [16][132];
    __shared__ float Wps[16][68];
    __shared__ float Wgs[16][68];
    __shared__ float w1s[CC], b1s[CC];

    const int tid = threadIdx.x;
    const int tx = tid & 15, ty = tid >> 4;
    const int m0  = blockIdx.x * 128;
    const int c0  = blockIdx.y * 64;
    const int off = blockIdx.z;                 // 0 -> 'a' (even), 1 -> 'b' (odd)
    float* __restrict__ dst = off ? g_BT : g_AT;

    if (tid < CC) { w1s[tid] = w1[tid]; b1s[tid] = b1[tid]; }

    const int lrow = tid >> 1;                  // 0..127
    const int lk   = (tid & 1) * 8;             // 0 or 8
    const float lmu = g_mu1[m0 + lrow];
    const float lrs = g_rs1[m0 + lrow];
    const float* prow = pair + (size_t)(m0 + lrow) * CC;

    const int wc = tid >> 2;                    // 0..63
    const int wk = (tid & 3) * 4;               // 0,4,8,12
    const float* wprow = Wp + (size_t)(2 * (c0 + wc) + off) * CC;
    const float* wgrow = Wg + (size_t)(2 * (c0 + wc) + off) * CC;

    float accp[8][4], accg[8][4];
    #pragma unroll
    for (int i = 0; i < 8; i++)
        #pragma unroll
        for (int j = 0; j < 4; j++) { accp[i][j] = 0.0f; accg[i][j] = 0.0f; }

    __syncthreads();

    for (int kt = 0; kt < CC; kt += 16) {
        float4 xa = *reinterpret_cast<const float4*>(prow + kt + lk);
        float4 xb = *reinterpret_cast<const float4*>(prow + kt + lk + 4);
        Xs[lk+0][lrow] = (xa.x - lmu) * lrs * w1s[kt+lk+0] + b1s[kt+lk+0];
        Xs[lk+1][lrow] = (xa.y - lmu) * lrs * w1s[kt+lk+1] + b1s[kt+lk+1];
        Xs[lk+2][lrow] = (xa.z - lmu) * lrs * w1s[kt+lk+2] + b1s[kt+lk+2];
        Xs[lk+3][lrow] = (xa.w - lmu) * lrs * w1s[kt+lk+3] + b1s[kt+lk+3];
        Xs[lk+4][lrow] = (xb.x - lmu) * lrs * w1s[kt+lk+4] + b1s[kt+lk+4];
        Xs[lk+5][lrow] = (xb.y - lmu) * lrs * w1s[kt+lk+5] + b1s[kt+lk+5];
        Xs[lk+6][lrow] = (xb.z - lmu) * lrs * w1s[kt+lk+6] + b1s[kt+lk+6];
        Xs[lk+7][lrow] = (xb.w - lmu) * lrs * w1s[kt+lk+7] + b1s[kt+lk+7];

        float4 p4 = *reinterpret_cast<const float4*>(wprow + kt + wk);
        float4 g4 = *reinterpret_cast<const float4*>(wgrow + kt + wk);
        Wps[wk+0][wc] = p4.x; Wps[wk+1][wc] = p4.y; Wps[wk+2][wc] = p4.z; Wps[wk+3][wc] = p4.w;
        Wgs[wk+0][wc] = g4.x; Wgs[wk+1][wc] = g4.y; Wgs[wk+2][wc] = g4.z; Wgs[wk+3][wc] = g4.w;
        __syncthreads();

        #pragma unroll
        for (int kk = 0; kk < 16; kk++) {
            float fx[8];
            #pragma unroll
            for (int i = 0; i < 8; i++) fx[i] = Xs[kk][tx + 16*i];
            float fp[4], fg[4];
            #pragma unroll
            for (int j = 0; j < 4; j++) { fp[j] = Wps[kk][ty + 16*j]; fg[j] = Wgs[kk][ty + 16*j]; }
            #pragma unroll
            for (int i = 0; i < 8; i++)
                #pragma unroll
                for (int j = 0; j < 4; j++) {
                    accp[i][j] += fx[i] * fp[j];
                    accg[i][j] += fx[i] * fg[j];
                }
        }
        __syncthreads();
    }

    #pragma unroll
    for (int i = 0; i < 8; i++) {
        int row = m0 + tx + 16*i;
        float mk = mask[row];
        #pragma unroll
        for (int j = 0; j < 4; j++) {
            int c = c0 + ty + 16*j;
            float av = accp[i][j] * mk * sigmoidf_(accg[i][j]);
            dst[(size_t)c * MM + row] = av;
        }
    }
}

// ---------------- gl gate GEMM: GL = sigmoid(x @ Wgl^T), (M,C) layout -------
__global__ __launch_bounds__(256) void k_gl(const float* __restrict__ pair,
                                            const float* __restrict__ w1,
                                            const float* __restrict__ b1,
                                            const float* __restrict__ Wgl) {
    __shared__ float Xs[16][132];
    __shared__ float Ws[16][68];
    __shared__ float w1s[CC], b1s[CC];

    const int tid = threadIdx.x;
    const int tx = tid & 15, ty = tid >> 4;
    const int m0 = blockIdx.x * 128;
    const int c0 = blockIdx.y * 64;

    if (tid < CC) { w1s[tid] = w1[tid]; b1s[tid] = b1[tid]; }

    const int lrow = tid >> 1;
    const int lk   = (tid & 1) * 8;
    const float lmu = g_mu1[m0 + lrow];
    const float lrs = g_rs1[m0 + lrow];
    const float* prow = pair + (size_t)(m0 + lrow) * CC;

    const int wc = tid >> 2;
    const int wk = (tid & 3) * 4;
    const float* wrow = Wgl + (size_t)(c0 + wc) * CC;

    float acc[8][4];
    #pragma unroll
    for (int i = 0; i < 8; i++)
        #pragma unroll
        for (int j = 0; j < 4; j++) acc[i][j] = 0.0f;

    __syncthreads();

    for (int kt = 0; kt < CC; kt += 16) {
        float4 xa = *reinterpret_cast<const float4*>(prow + kt + lk);
        float4 xb = *reinterpret_cast<const float4*>(prow + kt + lk + 4);
        Xs[lk+0][lrow] = (xa.x - lmu) * lrs * w1s[kt+lk+0] + b1s[kt+lk+0];
        Xs[lk+1][lrow] = (xa.y - lmu) * lrs * w1s[kt+lk+1] + b1s[kt+lk+1];
        Xs[lk+2][lrow] = (xa.z - lmu) * lrs * w1s[kt+lk+2] + b1s[kt+lk+2];
        Xs[lk+3][lrow] = (xa.w - lmu) * lrs * w1s[kt+lk+3] + b1s[kt+lk+3];
        Xs[lk+4][lrow] = (xb.x - lmu) * lrs * w1s[kt+lk+4] + b1s[kt+lk+4];
        Xs[lk+5][lrow] = (xb.y - lmu) * lrs * w1s[kt+lk+5] + b1s[kt+lk+5];
        Xs[lk+6][lrow] = (xb.z - lmu) * lrs * w1s[kt+lk+6] + b1s[kt+lk+6];
        Xs[lk+7][lrow] = (xb.w - lmu) * lrs * w1s[kt+lk+7] + b1s[kt+lk+7];

        float4 w4 = *reinterpret_cast<const float4*>(wrow + kt + wk);
        Ws[wk+0][wc] = w4.x; Ws[wk+1][wc] = w4.y; Ws[wk+2][wc] = w4.z; Ws[wk+3][wc] = w4.w;
        __syncthreads();

        #pragma unroll
        for (int kk = 0; kk < 16; kk++) {
            float fx[8];
            #pragma unroll
            for (int i = 0; i < 8; i++) fx[i] = Xs[kk][ty + 16*i];
            float fw[4];
            #pragma unroll
            for (int j = 0; j < 4; j++) fw[j] = Ws[kk][tx + 16*j];
            #pragma unroll
            for (int i = 0; i < 8; i++)
                #pragma unroll
                for (int j = 0; j < 4; j++) acc[i][j] += fx[i] * fw[j];
        }
        __syncthreads();
    }

    #pragma unroll
    for (int i = 0; i < 8; i++) {
        int row = m0 + ty + 16*i;
        #pragma unroll
        for (int j = 0; j < 4; j++) {
            int c = c0 + tx + 16*j;
            g_GL[(size_t)row * CC + c] = sigmoidf_(acc[i][j]);
        }
    }
}

// ---------------- triangle einsum: 128 batched 512x512x512 SGEMMs ----------
// TRIT[c,i,j] = sum_k AT[c,i,k] * BT[c,j,k]
__global__ __launch_bounds__(256) void k_tri() {
    __shared__ float As[16][132];
    __shared__ float Bs[16][132];

    const int tid = threadIdx.x;
    const int tx = tid & 15, ty = tid >> 4;
    const int c  = blockIdx.z;
    const int i0 = blockIdx.y * 128;
    const int j0 = blockIdx.x * 128;

    const float* __restrict__ A = g_AT + (size_t)c * MM;
    const float* __restrict__ B = g_BT + (size_t)c * MM;

    const int lrow = tid >> 1;
    const int lk   = (tid & 1) * 8;
    const float* arow = A + (size_t)(i0 + lrow) * NN;
    const float* brow = B + (size_t)(j0 + lrow) * NN;

    float acc[8][8];
    #pragma unroll
    for (int i = 0; i < 8; i++)
        #pragma unroll
        for (int j = 0; j < 8; j++) acc[i][j] = 0.0f;

    for (int kt = 0; kt < NN; kt += 16) {
        float4 a0 = *reinterpret_cast<const float4*>(arow + kt + lk);
        float4 a1 = *reinterpret_cast<const float4*>(arow + kt + lk + 4);
        float4 b0 = *reinterpret_cast<const float4*>(brow + kt + lk);
        float4 bv = *reinterpret_cast<const float4*>(brow + kt + lk + 4);
        As[lk+0][lrow] = a0.x; As[lk+1][lrow] = a0.y; As[lk+2][lrow] = a0.z; As[lk+3][lrow] = a0.w;
        As[lk+4][lrow] = a1.x; As[lk+5][lrow] = a1.y; As[lk+6][lrow] = a1.z; As[lk+7][lrow] = a1.w;
        Bs[lk+0][lrow] = b0.x; Bs[lk+1][lrow] = b0.y; Bs[lk+2][lrow] = b0.z; Bs[lk+3][lrow] = b0.w;
        Bs[lk+4][lrow] = bv.x; Bs[lk+5][lrow] = bv.y; Bs[lk+6][lrow] = bv.z; Bs[lk+7][lrow] = bv.w;
        __syncthreads();

        #pragma unroll
        for (int kk = 0; kk < 16; kk++) {
            float fa[8], fb[8];
            #pragma unroll
            for (int i = 0; i < 8; i++) fa[i] = As[kk][ty + 16*i];
            #pragma unroll
            for (int j = 0; j < 8; j++) fb[j] = Bs[kk][tx + 16*j];
            #pragma unroll
            for (int i = 0; i < 8; i++)
                #pragma unroll
                for (int j = 0; j < 8; j++) acc[i][j] += fa[i] * fb[j];
        }
        __syncthreads();
    }

    #pragma unroll
    for (int i = 0; i < 8; i++) {
        size_t base = (size_t)c * MM + (size_t)(i0 + ty + 16*i) * NN + j0;
        #pragma unroll
        for (int j = 0; j < 8; j++)
            g_TRIT[base + tx + 16*j] = acc[i][j];
    }
}

// ---------------- transpose (C, M) -> (M, C) --------------------------------
__global__ void k_transpose() {
    __shared__ float t[32][33];
    const int m0 = blockIdx.x * 32;
    const int c0 = blockIdx.y * 32;
    const int x = threadIdx.x, y = threadIdx.y;   // 32 x 8
    #pragma unroll
    for (int r = 0; r < 4; r++) {
        int c = c0 + y + 8*r;
        t[y + 8*r][x] = g_TRIT[(size_t)c * MM + m0 + x];
    }
    __syncthreads();
    #pragma unroll
    for (int r = 0; r < 4; r++) {
        int m = m0 + y + 8*r;
        g_TRI[(size_t)m * CC + c0 + x] = t[x][y + 8*r];
    }
}

// ---------------- output: LN2 on-the-fly, @Wo^T, * GL, + pair --------------
__global__ __launch_bounds__(256) void k_out(const float* __restrict__ pair,
                                             const float* __restrict__ w2,
                                             const float* __restrict__ b2,
                                             const float* __restrict__ Wo,
                                             float* __restrict__ out) {
    __shared__ float Ys[16][132];
    __shared__ float Ws[16][132];
    __shared__ float w2s[CC], b2s[CC];

    const int tid = threadIdx.x;
    const int tx = tid & 15, ty = tid >> 4;
    const int m0 = blockIdx.x * 128;

    if (tid < CC) { w2s[tid] = w2[tid]; b2s[tid] = b2[tid]; }

    const int lrow = tid >> 1;
    const int lk   = (tid & 1) * 8;
    const float lmu = g_mu2[m0 + lrow];
    const float lrs = g_rs2[m0 + lrow];
    const float* trow = g_TRI + (size_t)(m0 + lrow) * CC;
    const float* worow = Wo + (size_t)lrow * CC;   // output-channel row = lrow (0..127)

    float acc[8][8];
    #pragma unroll
    for (int i = 0; i < 8; i++)
        #pragma unroll
        for (int j = 0; j < 8; j++) acc[i][j] = 0.0f;

    __syncthreads();

    for (int kt = 0; kt < CC; kt += 16) {
        float4 ya = *reinterpret_cast<const float4*>(trow + kt + lk);
        float4 yb = *reinterpret_cast<const float4*>(trow + kt + lk + 4);
        Ys[lk+0][lrow] = (ya.x - lmu) * lrs * w2s[kt+lk+0] + b2s[kt+lk+0];
        Ys[lk+1][lrow] = (ya.y - lmu) * lrs * w2s[kt+lk+1] + b2s[kt+lk+1];
        Ys[lk+2][lrow] = (ya.z - lmu) * lrs * w2s[kt+lk+2] + b2s[kt+lk+2];
        Ys[lk+3][lrow] = (ya.w - lmu) * lrs * w2s[kt+lk+3] + b2s[kt+lk+3];
        Ys[lk+4][lrow] = (yb.x - lmu) * lrs * w2s[kt+lk+4] + b2s[kt+lk+4];
        Ys[lk+5][lrow] = (yb.y - lmu) * lrs * w2s[kt+lk+5] + b2s[kt+lk+5];
        Ys[lk+6][lrow] = (yb.z - lmu) * lrs * w2s[kt+lk+6] + b2s[kt+lk+6];
        Ys[lk+7][lrow] = (yb.w - lmu) * lrs * w2s[kt+lk+7] + b2s[kt+lk+7];

        float4 w4a = *reinterpret_cast<const float4*>(worow + kt + lk);
        float4 w4b = *reinterpret_cast<const float4*>(worow + kt + lk + 4);
        Ws[lk+0][lrow] = w4a.x; Ws[lk+1][lrow] = w4a.y; Ws[lk+2][lrow] = w4a.z; Ws[lk+3][lrow] = w4a.w;
        Ws[lk+4][lrow] = w4b.x; Ws[lk+5][lrow] = w4b.y; Ws[lk+6][lrow] = w4b.z; Ws[lk+7][lrow] = w4b.w;
        __syncthreads();

        #pragma unroll
        for (int kk = 0; kk < 16; kk++) {
            float fy[8], fw[8];
            #pragma unroll
            for (int i = 0; i < 8; i++) fy[i] = Ys[kk][ty + 16*i];
            #pragma unroll
            for (int j = 0; j < 8; j++) fw[j] = Ws[kk][tx + 16*j];
            #pragma unroll
            for (int i = 0; i < 8; i++)
                #pragma unroll
                for (int j = 0; j < 8; j++) acc[i][j] += fy[i] * fw[j];
        }
        __syncthreads();
    }

    #pragma unroll
    for (int i = 0; i < 8; i++) {
        int row = m0 + ty + 16*i;
        #pragma unroll
        for (int j = 0; j < 8; j++) {
            int o = tx + 16*j;
            size_t idx = (size_t)row * CC + o;
            out[idx] = pair[idx] + acc[i][j] * g_GL[idx];
        }
    }
}

// ---------------- launch --------------------------------------------------
extern "C" void kernel_launch(void* const* d_in, const int* in_sizes, int n_in,
                              void* d_out, int out_size) {
    const float* pair = (const float*)d_in[0];
    const float* mask = (const float*)d_in[1];
    const float* ln1w = (const float*)d_in[2];
    const float* ln1b = (const float*)d_in[3];
    const float* Wp   = (const float*)d_in[4];
    const float* Wg   = (const float*)d_in[5];
    const float* ln2w = (const float*)d_in[6];
    const float* ln2b = (const float*)d_in[7];
    const float* Wo   = (const float*)d_in[8];
    const float* Wgl  = (const float*)d_in[9];
    float* out = (float*)d_out;

    // 1) LN1 row stats over pair
    k_stats<<<MM / 8, 256>>>(pair, 0);

    // 2) proj/gate fused GEMM -> a (g_AT), b (g_BT), channel-major
    {
        dim3 g(MM / 128, 2, 2);
        k_proj<<<g, 256>>>(pair, mask, ln1w, ln1b, Wp, Wg);
    }

    // 3) gl gate GEMM -> g_GL (M, C)
    {
        dim3 g(MM / 128, 2);
        k_gl<<<g, 256>>>(pair, ln1w, ln1b, Wgl);
    }

    // 4) triangle einsum: 128 batched SGEMMs -> g_TRIT (C, N, N)
    {
        dim3 g(NN / 128, NN / 128, CC);
        k_tri<<<g, 256>>>();
    }

    // 5) transpose to (M, C)
    {
        dim3 g(MM / 32, CC / 32);
        k_transpose<<<g, dim3(32, 8)>>>();
    }

    // 6) LN2 row stats over g_TRI
    k_stats<<<MM / 8, 256>>>(nullptr, 1);

    // 7) output: LN2(tri) @ Wo^T * GL + pair
    k_out<<<MM / 128, 256>>>(pair, ln2w, ln2b, Wo, out);
}

// round 3
// speedup vs baseline: 1.2744x; 1.2744x over previous
#include <cuda_runtime.h>
#include <math.h>
#include <cstdint>

// Problem constants
#define NN 512
#define CC 128
#define MM (NN*NN)          // 262144 rows

// ---------------- scratch (device globals: allocation-free) ----------------
__device__ float g_AT[(size_t)CC * MM];
__device__ float g_BT[(size_t)CC * MM];
__device__ float g_GL[(size_t)CC * MM];
__device__ float g_TRIT[(size_t)CC * MM];
__device__ float g_TRI [(size_t)CC * MM];
__device__ float g_mu1[MM];
__device__ float g_rs1[MM];
__device__ float g_mu2[MM];
__device__ float g_rs2[MM];

__device__ __forceinline__ float sigmoidf_(float x) {
    return 1.0f / (1.0f + expf(-x));
}

// round-to-nearest tf32 (keeps value in a float reg; low mantissa bits zeroed)
__device__ __forceinline__ float to_tf32(float x) {
    uint32_t u;
    asm("cvt.rna.tf32.f32 %0, %1;" : "=r"(u) : "f"(x));
    return __uint_as_float(u);
}

__device__ __forceinline__ void mma_tf32(float d[4], const uint32_t a[4], const uint32_t b[2]) {
    asm volatile(
        "mma.sync.aligned.m16n8k8.row.col.f32.tf32.tf32.f32 "
        "{%0,%1,%2,%3}, {%4,%5,%6,%7}, {%8,%9}, {%0,%1,%2,%3};"
        : "+f"(d[0]), "+f"(d[1]), "+f"(d[2]), "+f"(d[3])
        : "r"(a[0]), "r"(a[1]), "r"(a[2]), "r"(a[3]), "r"(b[0]), "r"(b[1]));
}

// ---------------- LN row stats: one warp per 128-float row ----------------
__global__ __launch_bounds__(256) void k_stats(const float* __restrict__ src, int which) {
    const float* __restrict__ s = which ? (const float*)g_TRI : src;
    float* __restrict__ mu = which ? g_mu2 : g_mu1;
    float* __restrict__ rs = which ? g_rs2 : g_rs1;

    int row  = blockIdx.x * 8 + (threadIdx.x >> 5);
    int lane = threadIdx.x & 31;
    float4 v = reinterpret_cast<const float4*>(s + (size_t)row * CC)[lane];
    float sm = v.x + v.y + v.z + v.w;
    #pragma unroll
    for (int o = 16; o > 0; o >>= 1) sm += __shfl_xor_sync(0xffffffffu, sm, o);
    float m = sm * (1.0f / CC);
    float dx = v.x - m, dy = v.y - m, dz = v.z - m, dw = v.w - m;
    float q = dx*dx + dy*dy + dz*dz + dw*dw;
    #pragma unroll
    for (int o = 16; o > 0; o >>= 1) q += __shfl_xor_sync(0xffffffffu, q, o);
    if (lane == 0) {
        mu[row] = m;
        rs[row] = rsqrtf(q * (1.0f / CC) + 1e-5f);
    }
}

// ---------------- proj/gate GEMM, fused LN1 + mask + sigmoid gate ----------
__global__ __launch_bounds__(256) void k_proj(const float* __restrict__ pair,
                                              const float* __restrict__ mask,
                                              const float* __restrict__ w1,
                                              const float* __restrict__ b1,
                                              const float* __restrict__ Wp,
                                              const float* __restrict__ Wg) {
    __shared__ float Xs [16][132];
    __shared__ float Wps[16][68];
    __shared__ float Wgs[16][68];
    __shared__ float w1s[CC], b1s[CC];

    const int tid = threadIdx.x;
    const int tx = tid & 15, ty = tid >> 4;
    const int m0  = blockIdx.x * 128;
    const int c0  = blockIdx.y * 64;
    const int off = blockIdx.z;
    float* __restrict__ dst = off ? g_BT : g_AT;

    if (tid < CC) { w1s[tid] = w1[tid]; b1s[tid] = b1[tid]; }

    const int lrow = tid >> 1;
    const int lk   = (tid & 1) * 8;
    const float lmu = g_mu1[m0 + lrow];
    const float lrs = g_rs1[m0 + lrow];
    const float* prow = pair + (size_t)(m0 + lrow) * CC;

    const int wc = tid >> 2;
    const int wk = (tid & 3) * 4;
    const float* wprow = Wp + (size_t)(2 * (c0 + wc) + off) * CC;
    const float* wgrow = Wg + (size_t)(2 * (c0 + wc) + off) * CC;

    float accp[8][4], accg[8][4];
    #pragma unroll
    for (int i = 0; i < 8; i++)
        #pragma unroll
        for (int j = 0; j < 4; j++) { accp[i][j] = 0.0f; accg[i][j] = 0.0f; }

    __syncthreads();

    for (int kt = 0; kt < CC; kt += 16) {
        float4 xa = *reinterpret_cast<const float4*>(prow + kt + lk);
        float4 xb = *reinterpret_cast<const float4*>(prow + kt + lk + 4);
        Xs[lk+0][lrow] = (xa.x - lmu) * lrs * w1s[kt+lk+0] + b1s[kt+lk+0];
        Xs[lk+1][lrow] = (xa.y - lmu) * lrs * w1s[kt+lk+1] + b1s[kt+lk+1];
        Xs[lk+2][lrow] = (xa.z - lmu) * lrs * w1s[kt+lk+2] + b1s[kt+lk+2];
        Xs[lk+3][lrow] = (xa.w - lmu) * lrs * w1s[kt+lk+3] + b1s[kt+lk+3];
        Xs[lk+4][lrow] = (xb.x - lmu) * lrs * w1s[kt+lk+4] + b1s[kt+lk+4];
        Xs[lk+5][lrow] = (xb.y - lmu) * lrs * w1s[kt+lk+5] + b1s[kt+lk+5];
        Xs[lk+6][lrow] = (xb.z - lmu) * lrs * w1s[kt+lk+6] + b1s[kt+lk+6];
        Xs[lk+7][lrow] = (xb.w - lmu) * lrs * w1s[kt+lk+7] + b1s[kt+lk+7];

        float4 p4 = *reinterpret_cast<const float4*>(wprow + kt + wk);
        float4 g4 = *reinterpret_cast<const float4*>(wgrow + kt + wk);
        Wps[wk+0][wc] = p4.x; Wps[wk+1][wc] = p4.y; Wps[wk+2][wc] = p4.z; Wps[wk+3][wc] = p4.w;
        Wgs[wk+0][wc] = g4.x; Wgs[wk+1][wc] = g4.y; Wgs[wk+2][wc] = g4.z; Wgs[wk+3][wc] = g4.w;
        __syncthreads();

        #pragma unroll
        for (int kk = 0; kk < 16; kk++) {
            float fx[8];
            #pragma unroll
            for (int i = 0; i < 8; i++) fx[i] = Xs[kk][tx + 16*i];
            float fp[4], fg[4];
            #pragma unroll
            for (int j = 0; j < 4; j++) { fp[j] = Wps[kk][ty + 16*j]; fg[j] = Wgs[kk][ty + 16*j]; }
            #pragma unroll
            for (int i = 0; i < 8; i++)
                #pragma unroll
                for (int j = 0; j < 4; j++) {
                    accp[i][j] += fx[i] * fp[j];
                    accg[i][j] += fx[i] * fg[j];
                }
        }
        __syncthreads();
    }

    #pragma unroll
    for (int i = 0; i < 8; i++) {
        int row = m0 + tx + 16*i;
        float mk = mask[row];
        #pragma unroll
        for (int j = 0; j < 4; j++) {
            int c = c0 + ty + 16*j;
            float av = accp[i][j] * mk * sigmoidf_(accg[i][j]);
            dst[(size_t)c * MM + row] = av;
        }
    }
}

// ---------------- gl gate GEMM: GL = sigmoid(x @ Wgl^T), (M,C) layout -------
__global__ __launch_bounds__(256) void k_gl(const float* __restrict__ pair,
                                            const float* __restrict__ w1,
                                            const float* __restrict__ b1,
                                            const float* __restrict__ Wgl) {
    __shared__ float Xs[16][132];
    __shared__ float Ws[16][68];
    __shared__ float w1s[CC], b1s[CC];

    const int tid = threadIdx.x;
    const int tx = tid & 15, ty = tid >> 4;
    const int m0 = blockIdx.x * 128;
    const int c0 = blockIdx.y * 64;

    if (tid < CC) { w1s[tid] = w1[tid]; b1s[tid] = b1[tid]; }

    const int lrow = tid >> 1;
    const int lk   = (tid & 1) * 8;
    const float lmu = g_mu1[m0 + lrow];
    const float lrs = g_rs1[m0 + lrow];
    const float* prow = pair + (size_t)(m0 + lrow) * CC;

    const int wc = tid >> 2;
    const int wk = (tid & 3) * 4;
    const float* wrow = Wgl + (size_t)(c0 + wc) * CC;

    float acc[8][4];
    #pragma unroll
    for (int i = 0; i < 8; i++)
        #pragma unroll
        for (int j = 0; j < 4; j++) acc[i][j] = 0.0f;

    __syncthreads();

    for (int kt = 0; kt < CC; kt += 16) {
        float4 xa = *reinterpret_cast<const float4*>(prow + kt + lk);
        float4 xb = *reinterpret_cast<const float4*>(prow + kt + lk + 4);
        Xs[lk+0][lrow] = (xa.x - lmu) * lrs * w1s[kt+lk+0] + b1s[kt+lk+0];
        Xs[lk+1][lrow] = (xa.y - lmu) * lrs * w1s[kt+lk+1] + b1s[kt+lk+1];
        Xs[lk+2][lrow] = (xa.z - lmu) * lrs * w1s[kt+lk+2] + b1s[kt+lk+2];
        Xs[lk+3][lrow] = (xa.w - lmu) * lrs * w1s[kt+lk+3] + b1s[kt+lk+3];
        Xs[lk+4][lrow] = (xb.x - lmu) * lrs * w1s[kt+lk+4] + b1s[kt+lk+4];
        Xs[lk+5][lrow] = (xb.y - lmu) * lrs * w1s[kt+lk+5] + b1s[kt+lk+5];
        Xs[lk+6][lrow] = (xb.z - lmu) * lrs * w1s[kt+lk+6] + b1s[kt+lk+6];
        Xs[lk+7][lrow] = (xb.w - lmu) * lrs * w1s[kt+lk+7] + b1s[kt+lk+7];

        float4 w4 = *reinterpret_cast<const float4*>(wrow + kt + wk);
        Ws[wk+0][wc] = w4.x; Ws[wk+1][wc] = w4.y; Ws[wk+2][wc] = w4.z; Ws[wk+3][wc] = w4.w;
        __syncthreads();

        #pragma unroll
        for (int kk = 0; kk < 16; kk++) {
            float fx[8];
            #pragma unroll
            for (int i = 0; i < 8; i++) fx[i] = Xs[kk][ty + 16*i];
            float fw[4];
            #pragma unroll
            for (int j = 0; j < 4; j++) fw[j] = Ws[kk][tx + 16*j];
            #pragma unroll
            for (int i = 0; i < 8; i++)
                #pragma unroll
                for (int j = 0; j < 4; j++) acc[i][j] += fx[i] * fw[j];
        }
        __syncthreads();
    }

    #pragma unroll
    for (int i = 0; i < 8; i++) {
        int row = m0 + ty + 16*i;
        #pragma unroll
        for (int j = 0; j < 4; j++) {
            int c = c0 + tx + 16*j;
            g_GL[(size_t)row * CC + c] = sigmoidf_(acc[i][j]);
        }
    }
}

// ---------------- triangle einsum via mma.sync tf32 -------------------------
// TRIT[c,i,j] = sum_k AT[c,i,k] * BT[c,j,k]  (A @ B^T, both K-major)
// CTA: 128x128 tile, K-chunk 32. 8 warps in 2(m) x 4(n); warp tile 64x32.
#define KCH 32
#define SPAD 36   // 36 mod 32 = 4 -> conflict-free fragment loads
__global__ __launch_bounds__(256) void k_tri_mma() {
    __shared__ float As[128][SPAD];
    __shared__ float Bs[128][SPAD];

    const int tid  = threadIdx.x;
    const int wid  = tid >> 5;
    const int lane = tid & 31;
    const int wm   = wid >> 2;          // 0..1
    const int wn   = wid & 3;           // 0..3
    const int grp  = lane >> 2;         // 0..7
    const int qd   = lane & 3;          // 0..3

    const int c  = blockIdx.z;
    const int i0 = blockIdx.y * 128;
    const int j0 = blockIdx.x * 128;
    const float* __restrict__ A = g_AT + (size_t)c * MM + (size_t)i0 * NN;
    const float* __restrict__ B = g_BT + (size_t)c * MM + (size_t)j0 * NN;

    float d[4][4][4];
    #pragma unroll
    for (int mt = 0; mt < 4; mt++)
        #pragma unroll
        for (int nt = 0; nt < 4; nt++)
            #pragma unroll
            for (int r = 0; r < 4; r++) d[mt][nt][r] = 0.0f;

    for (int kt = 0; kt < NN / KCH; kt++) {
        // stage gmem -> regs (4 float4 per matrix per thread)
        float4 va[4], vb[4];
        #pragma unroll
        for (int r = 0; r < 4; r++) {
            int idx = tid + r * 256;     // 0..1023
            int row = idx >> 3;          // 0..127
            int q   = idx & 7;           // float4 slot in 32-float row
            va[r] = *reinterpret_cast<const float4*>(A + (size_t)row * NN + kt * KCH + q * 4);
            vb[r] = *reinterpret_cast<const float4*>(B + (size_t)row * NN + kt * KCH + q * 4);
        }
        __syncthreads();   // previous iteration's fragment reads complete
        #pragma unroll
        for (int r = 0; r < 4; r++) {
            int idx = tid + r * 256;
            int row = idx >> 3;
            int q   = idx & 7;
            float4 ta = make_float4(to_tf32(va[r].x), to_tf32(va[r].y),
                                    to_tf32(va[r].z), to_tf32(va[r].w));
            float4 tb = make_float4(to_tf32(vb[r].x), to_tf32(vb[r].y),
                                    to_tf32(vb[r].z), to_tf32(vb[r].w));
            *reinterpret_cast<float4*>(&As[row][q * 4]) = ta;
            *reinterpret_cast<float4*>(&Bs[row][q * 4]) = tb;
        }
        __syncthreads();

        #pragma unroll
        for (int ks = 0; ks < KCH / 8; ks++) {
            const int kc = ks * 8 + qd;
            uint32_t af[4][4];
            #pragma unroll
            for (int mt = 0; mt < 4; mt++) {
                int rr = wm * 64 + mt * 16 + grp;
                af[mt][0] = __float_as_uint(As[rr    ][kc]);
                af[mt][1] = __float_as_uint(As[rr + 8][kc]);
                af[mt][2] = __float_as_uint(As[rr    ][kc + 4]);
                af[mt][3] = __float_as_uint(As[rr + 8][kc + 4]);
            }
            uint32_t bf[4][2];
            #pragma unroll
            for (int nt = 0; nt < 4; nt++) {
                int nn = wn * 32 + nt * 8 + grp;
                bf[nt][0] = __float_as_uint(Bs[nn][kc]);
                bf[nt][1] = __float_as_uint(Bs[nn][kc + 4]);
            }
            #pragma unroll
            for (int mt = 0; mt < 4; mt++)
                #pragma unroll
                for (int nt = 0; nt < 4; nt++)
                    mma_tf32(d[mt][nt], af[mt], bf[nt]);
        }
    }

    // epilogue: write 128x128 tile
    float* __restrict__ D = g_TRIT + (size_t)c * MM;
    #pragma unroll
    for (int mt = 0; mt < 4; mt++) {
        int r1 = i0 + wm * 64 + mt * 16 + grp;
        int r2 = r1 + 8;
        #pragma unroll
        for (int nt = 0; nt < 4; nt++) {
            int col = j0 + wn * 32 + nt * 8 + qd * 2;
            *reinterpret_cast<float2*>(D + (size_t)r1 * NN + col) = make_float2(d[mt][nt][0], d[mt][nt][1]);
            *reinterpret_cast<float2*>(D + (size_t)r2 * NN + col) = make_float2(d[mt][nt][2], d[mt][nt][3]);
        }
    }
}

// ---------------- transpose (C, M) -> (M, C) --------------------------------
__global__ void k_transpose() {
    __shared__ float t[32][33];
    const int m0 = blockIdx.x * 32;
    const int c0 = blockIdx.y * 32;
    const int x = threadIdx.x, y = threadIdx.y;   // 32 x 8
    #pragma unroll
    for (int r = 0; r < 4; r++) {
        int c = c0 + y + 8*r;
        t[y + 8*r][x] = g_TRIT[(size_t)c * MM + m0 + x];
    }
    __syncthreads();
    #pragma unroll
    for (int r = 0; r < 4; r++) {
        int m = m0 + y + 8*r;
        g_TRI[(size_t)m * CC + c0 + x] = t[x][y + 8*r];
    }
}

// ---------------- output: LN2 on-the-fly, @Wo^T, * GL, + pair --------------
__global__ __launch_bounds__(256) void k_out(const float* __restrict__ pair,
                                             const float* __restrict__ w2,
                                             const float* __restrict__ b2,
                                             const float* __restrict__ Wo,
                                             float* __restrict__ out) {
    __shared__ float Ys[16][132];
    __shared__ float Ws[16][132];
    __shared__ float w2s[CC], b2s[CC];

    const int tid = threadIdx.x;
    const int tx = tid & 15, ty = tid >> 4;
    const int m0 = blockIdx.x * 128;

    if (tid < CC) { w2s[tid] = w2[tid]; b2s[tid] = b2[tid]; }

    const int lrow = tid >> 1;
    const int lk   = (tid & 1) * 8;
    const float lmu = g_mu2[m0 + lrow];
    const float lrs = g_rs2[m0 + lrow];
    const float* trow = g_TRI + (size_t)(m0 + lrow) * CC;
    const float* worow = Wo + (size_t)lrow * CC;

    float acc[8][8];
    #pragma unroll
    for (int i = 0; i < 8; i++)
        #pragma unroll
        for (int j = 0; j < 8; j++) acc[i][j] = 0.0f;

    __syncthreads();

    for (int kt = 0; kt < CC; kt += 16) {
        float4 ya = *reinterpret_cast<const float4*>(trow + kt + lk);
        float4 yb = *reinterpret_cast<const float4*>(trow + kt + lk + 4);
        Ys[lk+0][lrow] = (ya.x - lmu) * lrs * w2s[kt+lk+0] + b2s[kt+lk+0];
        Ys[lk+1][lrow] = (ya.y - lmu) * lrs * w2s[kt+lk+1] + b2s[kt+lk+1];
        Ys[lk+2][lrow] = (ya.z - lmu) * lrs * w2s[kt+lk+2] + b2s[kt+lk+2];
        Ys[lk+3][lrow] = (ya.w - lmu) * lrs * w2s[kt+lk+3] + b2s[kt+lk+3];
        Ys[lk+4][lrow] = (yb.x - lmu) * lrs * w2s[kt+lk+4] + b2s[kt+lk+4];
        Ys[lk+5][lrow] = (yb.y - lmu) * lrs * w2s[kt+lk+5] + b2s[kt+lk+5];
        Ys[lk+6][lrow] = (yb.z - lmu) * lrs * w2s[kt+lk+6] + b2s[kt+lk+6];
        Ys[lk+7][lrow] = (yb.w - lmu) * lrs * w2s[kt+lk+7] + b2s[kt+lk+7];

        float4 w4a = *reinterpret_cast<const float4*>(worow + kt + lk);
        float4 w4b = *reinterpret_cast<const float4*>(worow + kt + lk + 4);
        Ws[lk+0][lrow] = w4a.x; Ws[lk+1][lrow] = w4a.y; Ws[lk+2][lrow] = w4a.z; Ws[lk+3][lrow] = w4a.w;
        Ws[lk+4][lrow] = w4b.x; Ws[lk+5][lrow] = w4b.y; Ws[lk+6][lrow] = w4b.z; Ws[lk+7][lrow] = w4b.w;
        __syncthreads();

        #pragma unroll
        for (int kk = 0; kk < 16; kk++) {
            float fy[8], fw[8];
            #pragma unroll
            for (int i = 0; i < 8; i++) fy[i] = Ys[kk][ty + 16*i];
            #pragma unroll
            for (int j = 0; j < 8; j++) fw[j] = Ws[kk][tx + 16*j];
            #pragma unroll
            for (int i = 0; i < 8; i++)
                #pragma unroll
                for (int j = 0; j < 8; j++) acc[i][j] += fy[i] * fw[j];
        }
        __syncthreads();
    }

    #pragma unroll
    for (int i = 0; i < 8; i++) {
        int row = m0 + ty + 16*i;
        #pragma unroll
        for (int j = 0; j < 8; j++) {
            int o = tx + 16*j;
            size_t idx = (size_t)row * CC + o;
            out[idx] = pair[idx] + acc[i][j] * g_GL[idx];
        }
    }
}

// ---------------- launch --------------------------------------------------
extern "C" void kernel_launch(void* const* d_in, const int* in_sizes, int n_in,
                              void* d_out, int out_size) {
    const float* pair = (const float*)d_in[0];
    const float* mask = (const float*)d_in[1];
    const float* ln1w = (const float*)d_in[2];
    const float* ln1b = (const float*)d_in[3];
    const float* Wp   = (const float*)d_in[4];
    const float* Wg   = (const float*)d_in[5];
    const float* ln2w = (const float*)d_in[6];
    const float* ln2b = (const float*)d_in[7];
    const float* Wo   = (const float*)d_in[8];
    const float* Wgl  = (const float*)d_in[9];
    float* out = (float*)d_out;

    // 1) LN1 row stats
    k_stats<<<MM / 8, 256>>>(pair, 0);

    // 2) proj/gate fused GEMM -> a (g_AT), b (g_BT), channel-major
    {
        dim3 g(MM / 128, 2, 2);
        k_proj<<<g, 256>>>(pair, mask, ln1w, ln1b, Wp, Wg);
    }

    // 3) gl gate GEMM -> g_GL (M, C)
    {
        dim3 g(MM / 128, 2);
        k_gl<<<g, 256>>>(pair, ln1w, ln1b, Wgl);
    }

    // 4) triangle einsum via mma.sync tf32 -> g_TRIT (C, N, N)
    {
        dim3 g(NN / 128, NN / 128, CC);
        k_tri_mma<<<g, 256>>>();
    }

    // 5) transpose to (M, C)
    {
        dim3 g(MM / 32, CC / 32);
        k_transpose<<<g, dim3(32, 8)>>>();
    }

    // 6) LN2 row stats
    k_stats<<<MM / 8, 256>>>(nullptr, 1);

    // 7) output: LN2(tri) @ Wo^T * GL + pair
    k_out<<<MM / 128, 256>>>(pair, ln2w, ln2b, Wo, out);
}

// round 4
// speedup vs baseline: 2.3321x; 1.8300x over previous
#include <cuda_runtime.h>
#include <math.h>
#include <cstdint>

// Problem constants
#define NN 512
#define CC 128
#define MM (NN*NN)          // 262144 rows

// ---------------- scratch (device globals: allocation-free) ----------------
__device__ float g_AT[(size_t)CC * MM];
__device__ float g_BT[(size_t)CC * MM];
__device__ float g_GL[(size_t)CC * MM];
__device__ float g_TRIT[(size_t)CC * MM];
__device__ float g_TRI [(size_t)CC * MM];
__device__ float g_mu1[MM];
__device__ float g_rs1[MM];
__device__ float g_mu2[MM];
__device__ float g_rs2[MM];

__device__ __forceinline__ float sigmoidf_(float x) {
    return 1.0f / (1.0f + expf(-x));
}

// round-to-nearest tf32 (keeps value in a float reg; low mantissa bits zeroed)
__device__ __forceinline__ float to_tf32(float x) {
    uint32_t u;
    asm("cvt.rna.tf32.f32 %0, %1;" : "=r"(u) : "f"(x));
    return __uint_as_float(u);
}

__device__ __forceinline__ void mma_tf32(float d[4], const uint32_t a[4], const uint32_t b[2]) {
    asm volatile(
        "mma.sync.aligned.m16n8k8.row.col.f32.tf32.tf32.f32 "
        "{%0,%1,%2,%3}, {%4,%5,%6,%7}, {%8,%9}, {%0,%1,%2,%3};"
        : "+f"(d[0]), "+f"(d[1]), "+f"(d[2]), "+f"(d[3])
        : "r"(a[0]), "r"(a[1]), "r"(a[2]), "r"(a[3]), "r"(b[0]), "r"(b[1]));
}

// ---------------- LN row stats: one warp per 128-float row ----------------
__global__ __launch_bounds__(256) void k_stats(const float* __restrict__ src, int which) {
    const float* __restrict__ s = which ? (const float*)g_TRI : src;
    float* __restrict__ mu = which ? g_mu2 : g_mu1;
    float* __restrict__ rs = which ? g_rs2 : g_rs1;

    int row  = blockIdx.x * 8 + (threadIdx.x >> 5);
    int lane = threadIdx.x & 31;
    float4 v = reinterpret_cast<const float4*>(s + (size_t)row * CC)[lane];
    float sm = v.x + v.y + v.z + v.w;
    #pragma unroll
    for (int o = 16; o > 0; o >>= 1) sm += __shfl_xor_sync(0xffffffffu, sm, o);
    float m = sm * (1.0f / CC);
    float dx = v.x - m, dy = v.y - m, dz = v.z - m, dw = v.w - m;
    float q = dx*dx + dy*dy + dz*dz + dw*dw;
    #pragma unroll
    for (int o = 16; o > 0; o >>= 1) q += __shfl_xor_sync(0xffffffffu, q, o);
    if (lane == 0) {
        mu[row] = m;
        rs[row] = rsqrtf(q * (1.0f / CC) + 1e-5f);
    }
}

// ---------------- proj/gate GEMM via mma.sync, fused LN1+mask+sigmoid -------
// CTA: 128 rows x 64 a-channels (for one of a/b). Dual accumulators share A.
// Warps 4(m) x 2(n): warp tile 32 rows x 32 channels (x2 for proj/gate).
__global__ __launch_bounds__(256) void k_proj_mma(const float* __restrict__ pair,
                                                  const float* __restrict__ mask,
                                                  const float* __restrict__ w1,
                                                  const float* __restrict__ b1,
                                                  const float* __restrict__ Wp,
                                                  const float* __restrict__ Wg) {
    __shared__ float As[128][36];
    __shared__ float Bs[128][36];   // rows 0..63: Wp chans, 64..127: Wg chans

    const int tid = threadIdx.x;
    const int wid = tid >> 5, lane = tid & 31;
    const int wm = wid >> 1, wn = wid & 1;
    const int grp = lane >> 2, qd = lane & 3;
    const int m0  = blockIdx.y * 128;
    const int c0  = (blockIdx.x & 1) * 64;
    const int off = blockIdx.x >> 1;

    float accP[2][4][4], accG[2][4][4];
    #pragma unroll
    for (int mt = 0; mt < 2; mt++)
        #pragma unroll
        for (int nt = 0; nt < 4; nt++)
            #pragma unroll
            for (int r = 0; r < 4; r++) { accP[mt][nt][r] = 0.0f; accG[mt][nt][r] = 0.0f; }

    for (int kt = 0; kt < 4; kt++) {
        float4 va[4], vb[4];
        float lmu[4], lrs[4];
        #pragma unroll
        for (int r = 0; r < 4; r++) {
            int idx = tid + r * 256, row = idx >> 3, q = idx & 7;
            va[r] = *reinterpret_cast<const float4*>(pair + (size_t)(m0 + row) * CC + kt * 32 + q * 4);
            lmu[r] = g_mu1[m0 + row];
            lrs[r] = g_rs1[m0 + row];
            const float* wr = (row < 64)
                ? Wp + (size_t)(2 * (c0 + row) + off) * CC
                : Wg + (size_t)(2 * (c0 + row - 64) + off) * CC;
            vb[r] = *reinterpret_cast<const float4*>(wr + kt * 32 + q * 4);
        }
        __syncthreads();   // prior mma fragment reads done
        #pragma unroll
        for (int r = 0; r < 4; r++) {
            int idx = tid + r * 256, row = idx >> 3, q = idx & 7;
            float4 wv = *reinterpret_cast<const float4*>(w1 + kt * 32 + q * 4);
            float4 bv = *reinterpret_cast<const float4*>(b1 + kt * 32 + q * 4);
            float4 ta = make_float4(
                to_tf32((va[r].x - lmu[r]) * lrs[r] * wv.x + bv.x),
                to_tf32((va[r].y - lmu[r]) * lrs[r] * wv.y + bv.y),
                to_tf32((va[r].z - lmu[r]) * lrs[r] * wv.z + bv.z),
                to_tf32((va[r].w - lmu[r]) * lrs[r] * wv.w + bv.w));
            float4 tb = make_float4(to_tf32(vb[r].x), to_tf32(vb[r].y),
                                    to_tf32(vb[r].z), to_tf32(vb[r].w));
            *reinterpret_cast<float4*>(&As[row][q * 4]) = ta;
            *reinterpret_cast<float4*>(&Bs[row][q * 4]) = tb;
        }
        __syncthreads();

        #pragma unroll
        for (int ks = 0; ks < 4; ks++) {
            const int kc = ks * 8 + qd;
            uint32_t af[2][4];
            #pragma unroll
            for (int mt = 0; mt < 2; mt++) {
                int rr = wm * 32 + mt * 16 + grp;
                af[mt][0] = __float_as_uint(As[rr    ][kc]);
                af[mt][1] = __float_as_uint(As[rr + 8][kc]);
                af[mt][2] = __float_as_uint(As[rr    ][kc + 4]);
                af[mt][3] = __float_as_uint(As[rr + 8][kc + 4]);
            }
            uint32_t bp[4][2], bg[4][2];
            #pragma unroll
            for (int nt = 0; nt < 4; nt++) {
                int nn = wn * 32 + nt * 8 + grp;
                bp[nt][0] = __float_as_uint(Bs[nn     ][kc]);
                bp[nt][1] = __float_as_uint(Bs[nn     ][kc + 4]);
                bg[nt][0] = __float_as_uint(Bs[64 + nn][kc]);
                bg[nt][1] = __float_as_uint(Bs[64 + nn][kc + 4]);
            }
            #pragma unroll
            for (int mt = 0; mt < 2; mt++)
                #pragma unroll
                for (int nt = 0; nt < 4; nt++) {
                    mma_tf32(accP[mt][nt], af[mt], bp[nt]);
                    mma_tf32(accG[mt][nt], af[mt], bg[nt]);
                }
        }
    }

    float* __restrict__ dst = off ? g_BT : g_AT;
    #pragma unroll
    for (int mt = 0; mt < 2; mt++) {
        int ra = m0 + wm * 32 + mt * 16 + grp;
        int rb = ra + 8;
        float mka = mask[ra], mkb = mask[rb];
        #pragma unroll
        for (int nt = 0; nt < 4; nt++) {
            int ch = c0 + wn * 32 + nt * 8 + 2 * qd;
            dst[(size_t)ch * MM + ra]       = accP[mt][nt][0] * mka * sigmoidf_(accG[mt][nt][0]);
            dst[(size_t)(ch + 1) * MM + ra] = accP[mt][nt][1] * mka * sigmoidf_(accG[mt][nt][1]);
            dst[(size_t)ch * MM + rb]       = accP[mt][nt][2] * mkb * sigmoidf_(accG[mt][nt][2]);
            dst[(size_t)(ch + 1) * MM + rb] = accP[mt][nt][3] * mkb * sigmoidf_(accG[mt][nt][3]);
        }
    }
}

// ---------------- gl gate GEMM via mma.sync: GL = sigmoid(x @ Wgl^T) --------
__global__ __launch_bounds__(256) void k_gl_mma(const float* __restrict__ pair,
                                                const float* __restrict__ w1,
                                                const float* __restrict__ b1,
                                                const float* __restrict__ Wgl) {
    __shared__ float As[128][36];
    __shared__ float Bs[64][36];

    const int tid = threadIdx.x;
    const int wid = tid >> 5, lane = tid & 31;
    const int wm = wid >> 1, wn = wid & 1;
    const int grp = lane >> 2, qd = lane & 3;
    const int m0 = blockIdx.y * 128;
    const int c0 = blockIdx.x * 64;

    float acc[2][4][4];
    #pragma unroll
    for (int mt = 0; mt < 2; mt++)
        #pragma unroll
        for (int nt = 0; nt < 4; nt++)
            #pragma unroll
            for (int r = 0; r < 4; r++) acc[mt][nt][r] = 0.0f;

    for (int kt = 0; kt < 4; kt++) {
        float4 va[4], vb[2];
        float lmu[4], lrs[4];
        #pragma unroll
        for (int r = 0; r < 4; r++) {
            int idx = tid + r * 256, row = idx >> 3, q = idx & 7;
            va[r] = *reinterpret_cast<const float4*>(pair + (size_t)(m0 + row) * CC + kt * 32 + q * 4);
            lmu[r] = g_mu1[m0 + row];
            lrs[r] = g_rs1[m0 + row];
        }
        #pragma unroll
        for (int r = 0; r < 2; r++) {
            int idx = tid + r * 256;            // 0..511
            int row = idx >> 3, q = idx & 7;    // row 0..63
            vb[r] = *reinterpret_cast<const float4*>(Wgl + (size_t)(c0 + row) * CC + kt * 32 + q * 4);
        }
        __syncthreads();
        #pragma unroll
        for (int r = 0; r < 4; r++) {
            int idx = tid + r * 256, row = idx >> 3, q = idx & 7;
            float4 wv = *reinterpret_cast<const float4*>(w1 + kt * 32 + q * 4);
            float4 bv = *reinterpret_cast<const float4*>(b1 + kt * 32 + q * 4);
            float4 ta = make_float4(
                to_tf32((va[r].x - lmu[r]) * lrs[r] * wv.x + bv.x),
                to_tf32((va[r].y - lmu[r]) * lrs[r] * wv.y + bv.y),
                to_tf32((va[r].z - lmu[r]) * lrs[r] * wv.z + bv.z),
                to_tf32((va[r].w - lmu[r]) * lrs[r] * wv.w + bv.w));
            *reinterpret_cast<float4*>(&As[row][q * 4]) = ta;
        }
        #pragma unroll
        for (int r = 0; r < 2; r++) {
            int idx = tid + r * 256, row = idx >> 3, q = idx & 7;
            float4 tb = make_float4(to_tf32(vb[r].x), to_tf32(vb[r].y),
                                    to_tf32(vb[r].z), to_tf32(vb[r].w));
            *reinterpret_cast<float4*>(&Bs[row][q * 4]) = tb;
        }
        __syncthreads();

        #pragma unroll
        for (int ks = 0; ks < 4; ks++) {
            const int kc = ks * 8 + qd;
            uint32_t af[2][4];
            #pragma unroll
            for (int mt = 0; mt < 2; mt++) {
                int rr = wm * 32 + mt * 16 + grp;
                af[mt][0] = __float_as_uint(As[rr    ][kc]);
                af[mt][1] = __float_as_uint(As[rr + 8][kc]);
                af[mt][2] = __float_as_uint(As[rr    ][kc + 4]);
                af[mt][3] = __float_as_uint(As[rr + 8][kc + 4]);
            }
            uint32_t bf[4][2];
            #pragma unroll
            for (int nt = 0; nt < 4; nt++) {
                int nn = wn * 32 + nt * 8 + grp;
                bf[nt][0] = __float_as_uint(Bs[nn][kc]);
                bf[nt][1] = __float_as_uint(Bs[nn][kc + 4]);
            }
            #pragma unroll
            for (int mt = 0; mt < 2; mt++)
                #pragma unroll
                for (int nt = 0; nt < 4; nt++)
                    mma_tf32(acc[mt][nt], af[mt], bf[nt]);
        }
    }

    #pragma unroll
    for (int mt = 0; mt < 2; mt++) {
        int ra = m0 + wm * 32 + mt * 16 + grp;
        int rb = ra + 8;
        #pragma unroll
        for (int nt = 0; nt < 4; nt++) {
            int ch = c0 + wn * 32 + nt * 8 + 2 * qd;
            *reinterpret_cast<float2*>(g_GL + (size_t)ra * CC + ch) =
                make_float2(sigmoidf_(acc[mt][nt][0]), sigmoidf_(acc[mt][nt][1]));
            *reinterpret_cast<float2*>(g_GL + (size_t)rb * CC + ch) =
                make_float2(sigmoidf_(acc[mt][nt][2]), sigmoidf_(acc[mt][nt][3]));
        }
    }
}

// ---------------- triangle einsum via mma.sync tf32 -------------------------
#define KCH 32
#define SPAD 36
__global__ __launch_bounds__(256) void k_tri_mma() {
    __shared__ float As[128][SPAD];
    __shared__ float Bs[128][SPAD];

    const int tid  = threadIdx.x;
    const int wid  = tid >> 5;
    const int lane = tid & 31;
    const int wm   = wid >> 2;
    const int wn   = wid & 3;
    const int grp  = lane >> 2;
    const int qd   = lane & 3;

    const int c  = blockIdx.z;
    const int i0 = blockIdx.y * 128;
    const int j0 = blockIdx.x * 128;
    const float* __restrict__ A = g_AT + (size_t)c * MM + (size_t)i0 * NN;
    const float* __restrict__ B = g_BT + (size_t)c * MM + (size_t)j0 * NN;

    float d[4][4][4];
    #pragma unroll
    for (int mt = 0; mt < 4; mt++)
        #pragma unroll
        for (int nt = 0; nt < 4; nt++)
            #pragma unroll
            for (int r = 0; r < 4; r++) d[mt][nt][r] = 0.0f;

    for (int kt = 0; kt < NN / KCH; kt++) {
        float4 va[4], vb[4];
        #pragma unroll
        for (int r = 0; r < 4; r++) {
            int idx = tid + r * 256;
            int row = idx >> 3;
            int q   = idx & 7;
            va[r] = *reinterpret_cast<const float4*>(A + (size_t)row * NN + kt * KCH + q * 4);
            vb[r] = *reinterpret_cast<const float4*>(B + (size_t)row * NN + kt * KCH + q * 4);
        }
        __syncthreads();
        #pragma unroll
        for (int r = 0; r < 4; r++) {
            int idx = tid + r * 256;
            int row = idx >> 3;
            int q   = idx & 7;
            float4 ta = make_float4(to_tf32(va[r].x), to_tf32(va[r].y),
                                    to_tf32(va[r].z), to_tf32(va[r].w));
            float4 tb = make_float4(to_tf32(vb[r].x), to_tf32(vb[r].y),
                                    to_tf32(vb[r].z), to_tf32(vb[r].w));
            *reinterpret_cast<float4*>(&As[row][q * 4]) = ta;
            *reinterpret_cast<float4*>(&Bs[row][q * 4]) = tb;
        }
        __syncthreads();

        #pragma unroll
        for (int ks = 0; ks < KCH / 8; ks++) {
            const int kc = ks * 8 + qd;
            uint32_t af[4][4];
            #pragma unroll
            for (int mt = 0; mt < 4; mt++) {
                int rr = wm * 64 + mt * 16 + grp;
                af[mt][0] = __float_as_uint(As[rr    ][kc]);
                af[mt][1] = __float_as_uint(As[rr + 8][kc]);
                af[mt][2] = __float_as_uint(As[rr    ][kc + 4]);
                af[mt][3] = __float_as_uint(As[rr + 8][kc + 4]);
            }
            uint32_t bf[4][2];
            #pragma unroll
            for (int nt = 0; nt < 4; nt++) {
                int nn = wn * 32 + nt * 8 + grp;
                bf[nt][0] = __float_as_uint(Bs[nn][kc]);
                bf[nt][1] = __float_as_uint(Bs[nn][kc + 4]);
            }
            #pragma unroll
            for (int mt = 0; mt < 4; mt++)
                #pragma unroll
                for (int nt = 0; nt < 4; nt++)
                    mma_tf32(d[mt][nt], af[mt], bf[nt]);
        }
    }

    float* __restrict__ D = g_TRIT + (size_t)c * MM;
    #pragma unroll
    for (int mt = 0; mt < 4; mt++) {
        int r1 = i0 + wm * 64 + mt * 16 + grp;
        int r2 = r1 + 8;
        #pragma unroll
        for (int nt = 0; nt < 4; nt++) {
            int col = j0 + wn * 32 + nt * 8 + qd * 2;
            *reinterpret_cast<float2*>(D + (size_t)r1 * NN + col) = make_float2(d[mt][nt][0], d[mt][nt][1]);
            *reinterpret_cast<float2*>(D + (size_t)r2 * NN + col) = make_float2(d[mt][nt][2], d[mt][nt][3]);
        }
    }
}

// ---------------- transpose (C, M) -> (M, C) --------------------------------
__global__ void k_transpose() {
    __shared__ float t[32][33];
    const int m0 = blockIdx.x * 32;
    const int c0 = blockIdx.y * 32;
    const int x = threadIdx.x, y = threadIdx.y;   // 32 x 8
    #pragma unroll
    for (int r = 0; r < 4; r++) {
        int c = c0 + y + 8*r;
        t[y + 8*r][x] = g_TRIT[(size_t)c * MM + m0 + x];
    }
    __syncthreads();
    #pragma unroll
    for (int r = 0; r < 4; r++) {
        int m = m0 + y + 8*r;
        g_TRI[(size_t)m * CC + c0 + x] = t[x][y + 8*r];
    }
}

// ---------------- output via mma.sync: LN2 @ Wo^T * GL + pair ---------------
__global__ __launch_bounds__(256) void k_out_mma(const float* __restrict__ pair,
                                                 const float* __restrict__ w2,
                                                 const float* __restrict__ b2,
                                                 const float* __restrict__ Wo,
                                                 float* __restrict__ out) {
    __shared__ float As[128][36];
    __shared__ float Bs[64][36];

    const int tid = threadIdx.x;
    const int wid = tid >> 5, lane = tid & 31;
    const int wm = wid >> 1, wn = wid & 1;
    const int grp = lane >> 2, qd = lane & 3;
    const int m0 = blockIdx.y * 128;
    const int c0 = blockIdx.x * 64;

    float acc[2][4][4];
    #pragma unroll
    for (int mt = 0; mt < 2; mt++)
        #pragma unroll
        for (int nt = 0; nt < 4; nt++)
            #pragma unroll
            for (int r = 0; r < 4; r++) acc[mt][nt][r] = 0.0f;

    for (int kt = 0; kt < 4; kt++) {
        float4 va[4], vb[2];
        float lmu[4], lrs[4];
        #pragma unroll
        for (int r = 0; r < 4; r++) {
            int idx = tid + r * 256, row = idx >> 3, q = idx & 7;
            va[r] = *reinterpret_cast<const float4*>(g_TRI + (size_t)(m0 + row) * CC + kt * 32 + q * 4);
            lmu[r] = g_mu2[m0 + row];
            lrs[r] = g_rs2[m0 + row];
        }
        #pragma unroll
        for (int r = 0; r < 2; r++) {
            int idx = tid + r * 256;
            int row = idx >> 3, q = idx & 7;
            vb[r] = *reinterpret_cast<const float4*>(Wo + (size_t)(c0 + row) * CC + kt * 32 + q * 4);
        }
        __syncthreads();
        #pragma unroll
        for (int r = 0; r < 4; r++) {
            int idx = tid + r * 256, row = idx >> 3, q = idx & 7;
            float4 wv = *reinterpret_cast<const float4*>(w2 + kt * 32 + q * 4);
            float4 bv = *reinterpret_cast<const float4*>(b2 + kt * 32 + q * 4);
            float4 ta = make_float4(
                to_tf32((va[r].x - lmu[r]) * lrs[r] * wv.x + bv.x),
                to_tf32((va[r].y - lmu[r]) * lrs[r] * wv.y + bv.y),
                to_tf32((va[r].z - lmu[r]) * lrs[r] * wv.z + bv.z),
                to_tf32((va[r].w - lmu[r]) * lrs[r] * wv.w + bv.w));
            *reinterpret_cast<float4*>(&As[row][q * 4]) = ta;
        }
        #pragma unroll
        for (int r = 0; r < 2; r++) {
            int idx = tid + r * 256, row = idx >> 3, q = idx & 7;
            float4 tb = make_float4(to_tf32(vb[r].x), to_tf32(vb[r].y),
                                    to_tf32(vb[r].z), to_tf32(vb[r].w));
            *reinterpret_cast<float4*>(&Bs[row][q * 4]) = tb;
        }
        __syncthreads();

        #pragma unroll
        for (int ks = 0; ks < 4; ks++) {
            const int kc = ks * 8 + qd;
            uint32_t af[2][4];
            #pragma unroll
            for (int mt = 0; mt < 2; mt++) {
                int rr = wm * 32 + mt * 16 + grp;
                af[mt][0] = __float_as_uint(As[rr    ][kc]);
                af[mt][1] = __float_as_uint(As[rr + 8][kc]);
                af[mt][2] = __float_as_uint(As[rr    ][kc + 4]);
                af[mt][3] = __float_as_uint(As[rr + 8][kc + 4]);
            }
            uint32_t bf[4][2];
            #pragma unroll
            for (int nt = 0; nt < 4; nt++) {
                int nn = wn * 32 + nt * 8 + grp;
                bf[nt][0] = __float_as_uint(Bs[nn][kc]);
                bf[nt][1] = __float_as_uint(Bs[nn][kc + 4]);
            }
            #pragma unroll
            for (int mt = 0; mt < 2; mt++)
                #pragma unroll
                for (int nt = 0; nt < 4; nt++)
                    mma_tf32(acc[mt][nt], af[mt], bf[nt]);
        }
    }

    #pragma unroll
    for (int mt = 0; mt < 2; mt++) {
        int ra = m0 + wm * 32 + mt * 16 + grp;
        int rb = ra + 8;
        #pragma unroll
        for (int nt = 0; nt < 4; nt++) {
            int o = c0 + wn * 32 + nt * 8 + 2 * qd;
            size_t ia = (size_t)ra * CC + o;
            size_t ib = (size_t)rb * CC + o;
            float2 gla = *reinterpret_cast<const float2*>(g_GL + ia);
            float2 glb = *reinterpret_cast<const float2*>(g_GL + ib);
            float2 pa  = *reinterpret_cast<const float2*>(pair + ia);
            float2 pb  = *reinterpret_cast<const float2*>(pair + ib);
            *reinterpret_cast<float2*>(out + ia) =
                make_float2(pa.x + acc[mt][nt][0] * gla.x, pa.y + acc[mt][nt][1] * gla.y);
            *reinterpret_cast<float2*>(out + ib) =
                make_float2(pb.x + acc[mt][nt][2] * glb.x, pb.y + acc[mt][nt][3] * glb.y);
        }
    }
}

// ---------------- launch --------------------------------------------------
extern "C" void kernel_launch(void* const* d_in, const int* in_sizes, int n_in,
                              void* d_out, int out_size) {
    const float* pair = (const float*)d_in[0];
    const float* mask = (const float*)d_in[1];
    const float* ln1w = (const float*)d_in[2];
    const float* ln1b = (const float*)d_in[3];
    const float* Wp   = (const float*)d_in[4];
    const float* Wg   = (const float*)d_in[5];
    const float* ln2w = (const float*)d_in[6];
    const float* ln2b = (const float*)d_in[7];
    const float* Wo   = (const float*)d_in[8];
    const float* Wgl  = (const float*)d_in[9];
    float* out = (float*)d_out;

    // 1) LN1 row stats
    k_stats<<<MM / 8, 256>>>(pair, 0);

    // 2) proj/gate fused GEMM (tensor) -> a (g_AT), b (g_BT), channel-major
    {
        dim3 g(4, MM / 128);
        k_proj_mma<<<g, 256>>>(pair, mask, ln1w, ln1b, Wp, Wg);
    }

    // 3) gl gate GEMM (tensor) -> g_GL (M, C)
    {
        dim3 g(2, MM / 128);
        k_gl_mma<<<g, 256>>>(pair, ln1w, ln1b, Wgl);
    }

    // 4) triangle einsum (tensor) -> g_TRIT (C, N, N)
    {
        dim3 g(NN / 128, NN / 128, CC);
        k_tri_mma<<<g, 256>>>();
    }

    // 5) transpose to (M, C)
    {
        dim3 g(MM / 32, CC / 32);
        k_transpose<<<g, dim3(32, 8)>>>();
    }

    // 6) LN2 row stats
    k_stats<<<MM / 8, 256>>>(nullptr, 1);

    // 7) output (tensor): LN2(tri) @ Wo^T * GL + pair
    k_out_mma<<<2 * (MM / 128) > 65535 ? dim3(2, MM / 128) : dim3(2, MM / 128), 256>>>(pair, ln2w, ln2b, Wo, out);
}

// round 5
// speedup vs baseline: 2.5657x; 1.1001x over previous
#include <cuda_runtime.h>
#include <math.h>
#include <cstdint>

// Problem constants
#define NN 512
#define CC 128
#define MM (NN*NN)          // 262144 rows

// ---------------- scratch (device globals: allocation-free) ----------------
__device__ float g_AT[(size_t)CC * MM];
__device__ float g_BT[(size_t)CC * MM];
__device__ float g_GL[(size_t)CC * MM];
__device__ float g_TRIT[(size_t)CC * MM];
__device__ float g_TRI [(size_t)CC * MM];
__device__ float g_mu1[MM];
__device__ float g_rs1[MM];
__device__ float g_mu2[MM];
__device__ float g_rs2[MM];

__device__ __forceinline__ float sigmoidf_(float x) {
    return 1.0f / (1.0f + expf(-x));
}

// round-to-nearest tf32 (keeps value in a float reg; low mantissa bits zeroed)
__device__ __forceinline__ float to_tf32(float x) {
    uint32_t u;
    asm("cvt.rna.tf32.f32 %0, %1;" : "=r"(u) : "f"(x));
    return __uint_as_float(u);
}

__device__ __forceinline__ void mma_tf32(float d[4], const uint32_t a[4], const uint32_t b[2]) {
    asm volatile(
        "mma.sync.aligned.m16n8k8.row.col.f32.tf32.tf32.f32 "
        "{%0,%1,%2,%3}, {%4,%5,%6,%7}, {%8,%9}, {%0,%1,%2,%3};"
        : "+f"(d[0]), "+f"(d[1]), "+f"(d[2]), "+f"(d[3])
        : "r"(a[0]), "r"(a[1]), "r"(a[2]), "r"(a[3]), "r"(b[0]), "r"(b[1]));
}

__device__ __forceinline__ uint32_t smem_u32(const void* p) {
    return (uint32_t)__cvta_generic_to_shared(p);
}
__device__ __forceinline__ void cp_async16(uint32_t sm, const void* gm) {
    asm volatile("cp.async.cg.shared.global [%0], [%1], 16;" :: "r"(sm), "l"(gm) : "memory");
}
__device__ __forceinline__ void cp_commit() {
    asm volatile("cp.async.commit_group;" ::: "memory");
}
template <int N>
__device__ __forceinline__ void cp_wait() {
    asm volatile("cp.async.wait_group %0;" :: "n"(N) : "memory");
}

// ---------------- LN row stats: one warp per 128-float row ----------------
__global__ __launch_bounds__(256) void k_stats(const float* __restrict__ src, int which) {
    const float* __restrict__ s = which ? (const float*)g_TRI : src;
    float* __restrict__ mu = which ? g_mu2 : g_mu1;
    float* __restrict__ rs = which ? g_rs2 : g_rs1;

    int row  = blockIdx.x * 8 + (threadIdx.x >> 5);
    int lane = threadIdx.x & 31;
    float4 v = reinterpret_cast<const float4*>(s + (size_t)row * CC)[lane];
    float sm = v.x + v.y + v.z + v.w;
    #pragma unroll
    for (int o = 16; o > 0; o >>= 1) sm += __shfl_xor_sync(0xffffffffu, sm, o);
    float m = sm * (1.0f / CC);
    float dx = v.x - m, dy = v.y - m, dz = v.z - m, dw = v.w - m;
    float q = dx*dx + dy*dy + dz*dz + dw*dw;
    #pragma unroll
    for (int o = 16; o > 0; o >>= 1) q += __shfl_xor_sync(0xffffffffu, q, o);
    if (lane == 0) {
        mu[row] = m;
        rs[row] = rsqrtf(q * (1.0f / CC) + 1e-5f);
    }
}

// ---------------- proj/gate GEMM via mma.sync, fused LN1+mask+sigmoid -------
// Outputs pre-rounded to tf32 so k_tri can consume them raw via cp.async.
__global__ __launch_bounds__(256) void k_proj_mma(const float* __restrict__ pair,
                                                  const float* __restrict__ mask,
                                                  const float* __restrict__ w1,
                                                  const float* __restrict__ b1,
                                                  const float* __restrict__ Wp,
                                                  const float* __restrict__ Wg) {
    __shared__ float As[128][36];
    __shared__ float Bs[128][36];   // rows 0..63: Wp chans, 64..127: Wg chans

    const int tid = threadIdx.x;
    const int wid = tid >> 5, lane = tid & 31;
    const int wm = wid >> 1, wn = wid & 1;
    const int grp = lane >> 2, qd = lane & 3;
    const int m0  = blockIdx.y * 128;
    const int c0  = (blockIdx.x & 1) * 64;
    const int off = blockIdx.x >> 1;

    float accP[2][4][4], accG[2][4][4];
    #pragma unroll
    for (int mt = 0; mt < 2; mt++)
        #pragma unroll
        for (int nt = 0; nt < 4; nt++)
            #pragma unroll
            for (int r = 0; r < 4; r++) { accP[mt][nt][r] = 0.0f; accG[mt][nt][r] = 0.0f; }

    for (int kt = 0; kt < 4; kt++) {
        float4 va[4], vb[4];
        float lmu[4], lrs[4];
        #pragma unroll
        for (int r = 0; r < 4; r++) {
            int idx = tid + r * 256, row = idx >> 3, q = idx & 7;
            va[r] = *reinterpret_cast<const float4*>(pair + (size_t)(m0 + row) * CC + kt * 32 + q * 4);
            lmu[r] = g_mu1[m0 + row];
            lrs[r] = g_rs1[m0 + row];
            const float* wr = (row < 64)
                ? Wp + (size_t)(2 * (c0 + row) + off) * CC
                : Wg + (size_t)(2 * (c0 + row - 64) + off) * CC;
            vb[r] = *reinterpret_cast<const float4*>(wr + kt * 32 + q * 4);
        }
        __syncthreads();
        #pragma unroll
        for (int r = 0; r < 4; r++) {
            int idx = tid + r * 256, row = idx >> 3, q = idx & 7;
            float4 wv = *reinterpret_cast<const float4*>(w1 + kt * 32 + q * 4);
            float4 bv = *reinterpret_cast<const float4*>(b1 + kt * 32 + q * 4);
            float4 ta = make_float4(
                to_tf32((va[r].x - lmu[r]) * lrs[r] * wv.x + bv.x),
                to_tf32((va[r].y - lmu[r]) * lrs[r] * wv.y + bv.y),
                to_tf32((va[r].z - lmu[r]) * lrs[r] * wv.z + bv.z),
                to_tf32((va[r].w - lmu[r]) * lrs[r] * wv.w + bv.w));
            float4 tb = make_float4(to_tf32(vb[r].x), to_tf32(vb[r].y),
                                    to_tf32(vb[r].z), to_tf32(vb[r].w));
            *reinterpret_cast<float4*>(&As[row][q * 4]) = ta;
            *reinterpret_cast<float4*>(&Bs[row][q * 4]) = tb;
        }
        __syncthreads();

        #pragma unroll
        for (int ks = 0; ks < 4; ks++) {
            const int kc = ks * 8 + qd;
            uint32_t af[2][4];
            #pragma unroll
            for (int mt = 0; mt < 2; mt++) {
                int rr = wm * 32 + mt * 16 + grp;
                af[mt][0] = __float_as_uint(As[rr    ][kc]);
                af[mt][1] = __float_as_uint(As[rr + 8][kc]);
                af[mt][2] = __float_as_uint(As[rr    ][kc + 4]);
                af[mt][3] = __float_as_uint(As[rr + 8][kc + 4]);
            }
            uint32_t bp[4][2], bg[4][2];
            #pragma unroll
            for (int nt = 0; nt < 4; nt++) {
                int nn = wn * 32 + nt * 8 + grp;
                bp[nt][0] = __float_as_uint(Bs[nn     ][kc]);
                bp[nt][1] = __float_as_uint(Bs[nn     ][kc + 4]);
                bg[nt][0] = __float_as_uint(Bs[64 + nn][kc]);
                bg[nt][1] = __float_as_uint(Bs[64 + nn][kc + 4]);
            }
            #pragma unroll
            for (int mt = 0; mt < 2; mt++)
                #pragma unroll
                for (int nt = 0; nt < 4; nt++) {
                    mma_tf32(accP[mt][nt], af[mt], bp[nt]);
                    mma_tf32(accG[mt][nt], af[mt], bg[nt]);
                }
        }
    }

    float* __restrict__ dst = off ? g_BT : g_AT;
    #pragma unroll
    for (int mt = 0; mt < 2; mt++) {
        int ra = m0 + wm * 32 + mt * 16 + grp;
        int rb = ra + 8;
        float mka = mask[ra], mkb = mask[rb];
        #pragma unroll
        for (int nt = 0; nt < 4; nt++) {
            int ch = c0 + wn * 32 + nt * 8 + 2 * qd;
            dst[(size_t)ch * MM + ra]       = to_tf32(accP[mt][nt][0] * mka * sigmoidf_(accG[mt][nt][0]));
            dst[(size_t)(ch + 1) * MM + ra] = to_tf32(accP[mt][nt][1] * mka * sigmoidf_(accG[mt][nt][1]));
            dst[(size_t)ch * MM + rb]       = to_tf32(accP[mt][nt][2] * mkb * sigmoidf_(accG[mt][nt][2]));
            dst[(size_t)(ch + 1) * MM + rb] = to_tf32(accP[mt][nt][3] * mkb * sigmoidf_(accG[mt][nt][3]));
        }
    }
}

// ---------------- gl gate GEMM via mma.sync: GL = sigmoid(x @ Wgl^T) --------
__global__ __launch_bounds__(256) void k_gl_mma(const float* __restrict__ pair,
                                                const float* __restrict__ w1,
                                                const float* __restrict__ b1,
                                                const float* __restrict__ Wgl) {
    __shared__ float As[128][36];
    __shared__ float Bs[64][36];

    const int tid = threadIdx.x;
    const int wid = tid >> 5, lane = tid & 31;
    const int wm = wid >> 1, wn = wid & 1;
    const int grp = lane >> 2, qd = lane & 3;
    const int m0 = blockIdx.y * 128;
    const int c0 = blockIdx.x * 64;

    float acc[2][4][4];
    #pragma unroll
    for (int mt = 0; mt < 2; mt++)
        #pragma unroll
        for (int nt = 0; nt < 4; nt++)
            #pragma unroll
            for (int r = 0; r < 4; r++) acc[mt][nt][r] = 0.0f;

    for (int kt = 0; kt < 4; kt++) {
        float4 va[4], vb[2];
        float lmu[4], lrs[4];
        #pragma unroll
        for (int r = 0; r < 4; r++) {
            int idx = tid + r * 256, row = idx >> 3, q = idx & 7;
            va[r] = *reinterpret_cast<const float4*>(pair + (size_t)(m0 + row) * CC + kt * 32 + q * 4);
            lmu[r] = g_mu1[m0 + row];
            lrs[r] = g_rs1[m0 + row];
        }
        #pragma unroll
        for (int r = 0; r < 2; r++) {
            int idx = tid + r * 256;
            int row = idx >> 3, q = idx & 7;
            vb[r] = *reinterpret_cast<const float4*>(Wgl + (size_t)(c0 + row) * CC + kt * 32 + q * 4);
        }
        __syncthreads();
        #pragma unroll
        for (int r = 0; r < 4; r++) {
            int idx = tid + r * 256, row = idx >> 3, q = idx & 7;
            float4 wv = *reinterpret_cast<const float4*>(w1 + kt * 32 + q * 4);
            float4 bv = *reinterpret_cast<const float4*>(b1 + kt * 32 + q * 4);
            float4 ta = make_float4(
                to_tf32((va[r].x - lmu[r]) * lrs[r] * wv.x + bv.x),
                to_tf32((va[r].y - lmu[r]) * lrs[r] * wv.y + bv.y),
                to_tf32((va[r].z - lmu[r]) * lrs[r] * wv.z + bv.z),
                to_tf32((va[r].w - lmu[r]) * lrs[r] * wv.w + bv.w));
            *reinterpret_cast<float4*>(&As[row][q * 4]) = ta;
        }
        #pragma unroll
        for (int r = 0; r < 2; r++) {
            int idx = tid + r * 256, row = idx >> 3, q = idx & 7;
            float4 tb = make_float4(to_tf32(vb[r].x), to_tf32(vb[r].y),
                                    to_tf32(vb[r].z), to_tf32(vb[r].w));
            *reinterpret_cast<float4*>(&Bs[row][q * 4]) = tb;
        }
        __syncthreads();

        #pragma unroll
        for (int ks = 0; ks < 4; ks++) {
            const int kc = ks * 8 + qd;
            uint32_t af[2][4];
            #pragma unroll
            for (int mt = 0; mt < 2; mt++) {
                int rr = wm * 32 + mt * 16 + grp;
                af[mt][0] = __float_as_uint(As[rr    ][kc]);
                af[mt][1] = __float_as_uint(As[rr + 8][kc]);
                af[mt][2] = __float_as_uint(As[rr    ][kc + 4]);
                af[mt][3] = __float_as_uint(As[rr + 8][kc + 4]);
            }
            uint32_t bf[4][2];
            #pragma unroll
            for (int nt = 0; nt < 4; nt++) {
                int nn = wn * 32 + nt * 8 + grp;
                bf[nt][0] = __float_as_uint(Bs[nn][kc]);
                bf[nt][1] = __float_as_uint(Bs[nn][kc + 4]);
            }
            #pragma unroll
            for (int mt = 0; mt < 2; mt++)
                #pragma unroll
                for (int nt = 0; nt < 4; nt++)
                    mma_tf32(acc[mt][nt], af[mt], bf[nt]);
        }
    }

    #pragma unroll
    for (int mt = 0; mt < 2; mt++) {
        int ra = m0 + wm * 32 + mt * 16 + grp;
        int rb = ra + 8;
        #pragma unroll
        for (int nt = 0; nt < 4; nt++) {
            int ch = c0 + wn * 32 + nt * 8 + 2 * qd;
            *reinterpret_cast<float2*>(g_GL + (size_t)ra * CC + ch) =
                make_float2(sigmoidf_(acc[mt][nt][0]), sigmoidf_(acc[mt][nt][1]));
            *reinterpret_cast<float2*>(g_GL + (size_t)rb * CC + ch) =
                make_float2(sigmoidf_(acc[mt][nt][2]), sigmoidf_(acc[mt][nt][3]));
        }
    }
}

// ---------------- triangle einsum: cp.async double-buffered mma.sync --------
// TRIT[c,i,j] = sum_k AT[c,i,k] * BT[c,j,k]; inputs are pre-rounded tf32.
// CTA 128x128 tile; K staged in 32 chunks of 16 with a 2-stage pipeline.
__global__ __launch_bounds__(256, 2) void k_tri_mma() {
    __shared__ float As[2][128][20];
    __shared__ float Bs[2][128][20];

    const int tid  = threadIdx.x;
    const int wid  = tid >> 5;
    const int lane = tid & 31;
    const int wm   = wid >> 2;          // 0..1
    const int wn   = wid & 3;           // 0..3
    const int grp  = lane >> 2;         // 0..7
    const int qd   = lane & 3;          // 0..3

    const int c  = blockIdx.z;
    const int i0 = blockIdx.y * 128;
    const int j0 = blockIdx.x * 128;
    const float* __restrict__ A = g_AT + (size_t)c * MM + (size_t)i0 * NN;
    const float* __restrict__ B = g_BT + (size_t)c * MM + (size_t)j0 * NN;

    // this thread's two copy slots: chunk id = tid + r*256 (512 chunks = 128 rows x 4)
    const int row0 = tid >> 2,        q0 = tid & 3;
    const int row1 = (tid + 256) >> 2, q1 = (tid + 256) & 3;

    float d[4][4][4];
    #pragma unroll
    for (int mt = 0; mt < 4; mt++)
        #pragma unroll
        for (int nt = 0; nt < 4; nt++)
            #pragma unroll
            for (int r = 0; r < 4; r++) d[mt][nt][r] = 0.0f;

    // prologue: stage kt=0 into buffer 0
    {
        cp_async16(smem_u32(&As[0][row0][q0 * 4]), A + (size_t)row0 * NN + q0 * 4);
        cp_async16(smem_u32(&Bs[0][row0][q0 * 4]), B + (size_t)row0 * NN + q0 * 4);
        cp_async16(smem_u32(&As[0][row1][q1 * 4]), A + (size_t)row1 * NN + q1 * 4);
        cp_async16(smem_u32(&Bs[0][row1][q1 * 4]), B + (size_t)row1 * NN + q1 * 4);
        cp_commit();
    }

    for (int kt = 0; kt < 32; kt++) {
        const int cur = kt & 1, nxt = cur ^ 1;
        if (kt < 31) {
            const int ko = (kt + 1) * 16;
            cp_async16(smem_u32(&As[nxt][row0][q0 * 4]), A + (size_t)row0 * NN + ko + q0 * 4);
            cp_async16(smem_u32(&Bs[nxt][row0][q0 * 4]), B + (size_t)row0 * NN + ko + q0 * 4);
            cp_async16(smem_u32(&As[nxt][row1][q1 * 4]), A + (size_t)row1 * NN + ko + q1 * 4);
            cp_async16(smem_u32(&Bs[nxt][row1][q1 * 4]), B + (size_t)row1 * NN + ko + q1 * 4);
            cp_commit();
            cp_wait<1>();
        } else {
            cp_wait<0>();
        }
        __syncthreads();

        #pragma unroll
        for (int ks = 0; ks < 2; ks++) {
            const int kc = ks * 8 + qd;
            uint32_t af[4][4];
            #pragma unroll
            for (int mt = 0; mt < 4; mt++) {
                int rr = wm * 64 + mt * 16 + grp;
                af[mt][0] = __float_as_uint(As[cur][rr    ][kc]);
                af[mt][1] = __float_as_uint(As[cur][rr + 8][kc]);
                af[mt][2] = __float_as_uint(As[cur][rr    ][kc + 4]);
                af[mt][3] = __float_as_uint(As[cur][rr + 8][kc + 4]);
            }
            uint32_t bf[4][2];
            #pragma unroll
            for (int nt = 0; nt < 4; nt++) {
                int nn = wn * 32 + nt * 8 + grp;
                bf[nt][0] = __float_as_uint(Bs[cur][nn][kc]);
                bf[nt][1] = __float_as_uint(Bs[cur][nn][kc + 4]);
            }
            #pragma unroll
            for (int mt = 0; mt < 4; mt++)
                #pragma unroll
                for (int nt = 0; nt < 4; nt++)
                    mma_tf32(d[mt][nt], af[mt], bf[nt]);
        }
        __syncthreads();   // all warps done with buf[cur] before it is refilled
    }

    float* __restrict__ D = g_TRIT + (size_t)c * MM;
    #pragma unroll
    for (int mt = 0; mt < 4; mt++) {
        int r1 = i0 + wm * 64 + mt * 16 + grp;
        int r2 = r1 + 8;
        #pragma unroll
        for (int nt = 0; nt < 4; nt++) {
            int col = j0 + wn * 32 + nt * 8 + qd * 2;
            *reinterpret_cast<float2*>(D + (size_t)r1 * NN + col) = make_float2(d[mt][nt][0], d[mt][nt][1]);
            *reinterpret_cast<float2*>(D + (size_t)r2 * NN + col) = make_float2(d[mt][nt][2], d[mt][nt][3]);
        }
    }
}

// ---------------- transpose (C, M) -> (M, C) --------------------------------
__global__ void k_transpose() {
    __shared__ float t[32][33];
    const int m0 = blockIdx.x * 32;
    const int c0 = blockIdx.y * 32;
    const int x = threadIdx.x, y = threadIdx.y;   // 32 x 8
    #pragma unroll
    for (int r = 0; r < 4; r++) {
        int c = c0 + y + 8*r;
        t[y + 8*r][x] = g_TRIT[(size_t)c * MM + m0 + x];
    }
    __syncthreads();
    #pragma unroll
    for (int r = 0; r < 4; r++) {
        int m = m0 + y + 8*r;
        g_TRI[(size_t)m * CC + c0 + x] = t[x][y + 8*r];
    }
}

// ---------------- output via mma.sync: LN2 @ Wo^T * GL + pair ---------------
__global__ __launch_bounds__(256) void k_out_mma(const float* __restrict__ pair,
                                                 const float* __restrict__ w2,
                                                 const float* __restrict__ b2,
                                                 const float* __restrict__ Wo,
                                                 float* __restrict__ out) {
    __shared__ float As[128][36];
    __shared__ float Bs[64][36];

    const int tid = threadIdx.x;
    const int wid = tid >> 5, lane = tid & 31;
    const int wm = wid >> 1, wn = wid & 1;
    const int grp = lane >> 2, qd = lane & 3;
    const int m0 = blockIdx.y * 128;
    const int c0 = blockIdx.x * 64;

    float acc[2][4][4];
    #pragma unroll
    for (int mt = 0; mt < 2; mt++)
        #pragma unroll
        for (int nt = 0; nt < 4; nt++)
            #pragma unroll
            for (int r = 0; r < 4; r++) acc[mt][nt][r] = 0.0f;

    for (int kt = 0; kt < 4; kt++) {
        float4 va[4], vb[2];
        float lmu[4], lrs[4];
        #pragma unroll
        for (int r = 0; r < 4; r++) {
            int idx = tid + r * 256, row = idx >> 3, q = idx & 7;
            va[r] = *reinterpret_cast<const float4*>(g_TRI + (size_t)(m0 + row) * CC + kt * 32 + q * 4);
            lmu[r] = g_mu2[m0 + row];
            lrs[r] = g_rs2[m0 + row];
        }
        #pragma unroll
        for (int r = 0; r < 2; r++) {
            int idx = tid + r * 256;
            int row = idx >> 3, q = idx & 7;
            vb[r] = *reinterpret_cast<const float4*>(Wo + (size_t)(c0 + row) * CC + kt * 32 + q * 4);
        }
        __syncthreads();
        #pragma unroll
        for (int r = 0; r < 4; r++) {
            int idx = tid + r * 256, row = idx >> 3, q = idx & 7;
            float4 wv = *reinterpret_cast<const float4*>(w2 + kt * 32 + q * 4);
            float4 bv = *reinterpret_cast<const float4*>(b2 + kt * 32 + q * 4);
            float4 ta = make_float4(
                to_tf32((va[r].x - lmu[r]) * lrs[r] * wv.x + bv.x),
                to_tf32((va[r].y - lmu[r]) * lrs[r] * wv.y + bv.y),
                to_tf32((va[r].z - lmu[r]) * lrs[r] * wv.z + bv.z),
                to_tf32((va[r].w - lmu[r]) * lrs[r] * wv.w + bv.w));
            *reinterpret_cast<float4*>(&As[row][q * 4]) = ta;
        }
        #pragma unroll
        for (int r = 0; r < 2; r++) {
            int idx = tid + r * 256, row = idx >> 3, q = idx & 7;
            float4 tb = make_float4(to_tf32(vb[r].x), to_tf32(vb[r].y),
                                    to_tf32(vb[r].z), to_tf32(vb[r].w));
            *reinterpret_cast<float4*>(&Bs[row][q * 4]) = tb;
        }
        __syncthreads();

        #pragma unroll
        for (int ks = 0; ks < 4; ks++) {
            const int kc = ks * 8 + qd;
            uint32_t af[2][4];
            #pragma unroll
            for (int mt = 0; mt < 2; mt++) {
                int rr = wm * 32 + mt * 16 + grp;
                af[mt][0] = __float_as_uint(As[rr    ][kc]);
                af[mt][1] = __float_as_uint(As[rr + 8][kc]);
                af[mt][2] = __float_as_uint(As[rr    ][kc + 4]);
                af[mt][3] = __float_as_uint(As[rr + 8][kc + 4]);
            }
            uint32_t bf[4][2];
            #pragma unroll
            for (int nt = 0; nt < 4; nt++) {
                int nn = wn * 32 + nt * 8 + grp;
                bf[nt][0] = __float_as_uint(Bs[nn][kc]);
                bf[nt][1] = __float_as_uint(Bs[nn][kc + 4]);
            }
            #pragma unroll
            for (int mt = 0; mt < 2; mt++)
                #pragma unroll
                for (int nt = 0; nt < 4; nt++)
                    mma_tf32(acc[mt][nt], af[mt], bf[nt]);
        }
    }

    #pragma unroll
    for (int mt = 0; mt < 2; mt++) {
        int ra = m0 + wm * 32 + mt * 16 + grp;
        int rb = ra + 8;
        #pragma unroll
        for (int nt = 0; nt < 4; nt++) {
            int o = c0 + wn * 32 + nt * 8 + 2 * qd;
            size_t ia = (size_t)ra * CC + o;
            size_t ib = (size_t)rb * CC + o;
            float2 gla = *reinterpret_cast<const float2*>(g_GL + ia);
            float2 glb = *reinterpret_cast<const float2*>(g_GL + ib);
            float2 pa  = *reinterpret_cast<const float2*>(pair + ia);
            float2 pb  = *reinterpret_cast<const float2*>(pair + ib);
            *reinterpret_cast<float2*>(out + ia) =
                make_float2(pa.x + acc[mt][nt][0] * gla.x, pa.y + acc[mt][nt][1] * gla.y);
            *reinterpret_cast<float2*>(out + ib) =
                make_float2(pb.x + acc[mt][nt][2] * glb.x, pb.y + acc[mt][nt][3] * glb.y);
        }
    }
}

// ---------------- launch --------------------------------------------------
extern "C" void kernel_launch(void* const* d_in, const int* in_sizes, int n_in,
                              void* d_out, int out_size) {
    const float* pair = (const float*)d_in[0];
    const float* mask = (const float*)d_in[1];
    const float* ln1w = (const float*)d_in[2];
    const float* ln1b = (const float*)d_in[3];
    const float* Wp   = (const float*)d_in[4];
    const float* Wg   = (const float*)d_in[5];
    const float* ln2w = (const float*)d_in[6];
    const float* ln2b = (const float*)d_in[7];
    const float* Wo   = (const float*)d_in[8];
    const float* Wgl  = (const float*)d_in[9];
    float* out = (float*)d_out;

    // 1) LN1 row stats
    k_stats<<<MM / 8, 256>>>(pair, 0);

    // 2) proj/gate fused GEMM (tensor) -> a (g_AT), b (g_BT), channel-major tf32
    {
        dim3 g(4, MM / 128);
        k_proj_mma<<<g, 256>>>(pair, mask, ln1w, ln1b, Wp, Wg);
    }

    // 3) gl gate GEMM (tensor) -> g_GL (M, C)
    {
        dim3 g(2, MM / 128);
        k_gl_mma<<<g, 256>>>(pair, ln1w, ln1b, Wgl);
    }

    // 4) triangle einsum (tensor, cp.async pipelined) -> g_TRIT (C, N, N)
    {
        dim3 g(NN / 128, NN / 128, CC);
        k_tri_mma<<<g, 256>>>();
    }

    // 5) transpose to (M, C)
    {
        dim3 g(MM / 32, CC / 32);
        k_transpose<<<g, dim3(32, 8)>>>();
    }

    // 6) LN2 row stats
    k_stats<<<MM / 8, 256>>>(nullptr, 1);

    // 7) output (tensor): LN2(tri) @ Wo^T * GL + pair
    {
        dim3 g(2, MM / 128);
        k_out_mma<<<g, 256>>>(pair, ln2w, ln2b, Wo, out);
    }
}